// round 12
// baseline (speedup 1.0000x reference)
#include <cuda_runtime.h>
#include <cuda_bf16.h>

#define KK 26
#define DD 128
#define MM 256
#define BB 512
#define NRED 126         // reducer blocks (126*32 >= 4004 outputs)
#define KP 32            // padded row stride: 128B rows -> 16B-aligned LDS.128
#define WPAD 130         // padded W row stride (conflict-free LDS.64 per 16-lane phase)
#define OUTSZ (KK*DD + KK*KK)   // 4004

typedef unsigned long long u64;

__device__ float g_scratch[BB * OUTSZ];   // per-word gradients
__device__ int g_ctr  = 0;                // word-completion doorbell
__device__ int g_done = 0;                // reducer-completion counter

// ---- packed f32x2 helpers (FFMA2 path, sm_100a) ----
__device__ __forceinline__ u64 ffma2(u64 a, u64 b, u64 c) {
    u64 d;
    asm("fma.rn.f32x2 %0, %1, %2, %3;" : "=l"(d) : "l"(a), "l"(b), "l"(c));
    return d;
}
__device__ __forceinline__ u64 pk2(float lo, float hi) {
    u64 r; asm("mov.b64 %0, {%1, %2};" : "=l"(r) : "f"(lo), "f"(hi)); return r;
}
__device__ __forceinline__ float2 upk2(u64 v) {
    float2 f; asm("mov.b64 {%0, %1}, %2;" : "=f"(f.x), "=f"(f.y) : "l"(v)); return f;
}
__device__ __forceinline__ int ld_vol(const int* p) {
    int v; asm volatile("ld.volatile.global.s32 %0, [%1];" : "=r"(v) : "l"(p)); return v;
}

// ---- dynamic shared memory layout (floats) ----
#define SM_PS   0                      // [MM][KP] Ps, later Rres
#define SM_U    (SM_PS + MM*KP)        // [MM][KP] U,  later A
#define SM_V    (SM_U  + MM*KP)        // [MM][KP] V,  later B  (aliases Wsh in phase S)
#define SM_E    (SM_V  + MM*KP)        // [KK*KK]  exp(T)
#define SM_LAB  (SM_E  + KK*KK)        // [MM] int labels
#define SM_DEXP (SM_LAB + MM)          // [MM] int backward scale exponents
#define SM_CNT  (SM_DEXP + MM)         // [KK*KK] int transition counts
#define SM_TOT  (SM_CNT + KK*KK)       // 26440 floats = 105760 bytes

__global__ void __launch_bounds__(256, 2)
crf_fused_kernel(const float* __restrict__ data,
                 const int* __restrict__ labI,
                 const float* __restrict__ Wg,
                 const float* __restrict__ Tg,
                 float* __restrict__ out)
{
    extern __shared__ float sm[];
    const int t    = threadIdx.x;
    const int lane = t & 31;
    const int wid  = t >> 5;

    // ================= REDUCER BLOCKS =================
    if (blockIdx.x >= BB) {
        if (t == 0) {
            while (ld_vol(&g_ctr) < BB) __nanosleep(200);
        }
        __syncthreads();
        __threadfence();   // acquire: order scratch reads after doorbell

        float* red = sm;   // [8][33]
        const int ws = wid;
        const int og = (blockIdx.x - BB) * 32 + lane;
        float s0 = 0.f, s1 = 0.f, s2 = 0.f, s3 = 0.f;
        if (og < OUTSZ) {
            const float* p = g_scratch + (size_t)ws * 64 * OUTSZ + og;
            #pragma unroll 4
            for (int v = 0; v < 64; v += 4) {
                s0 += p[(size_t)(v + 0) * OUTSZ];
                s1 += p[(size_t)(v + 1) * OUTSZ];
                s2 += p[(size_t)(v + 2) * OUTSZ];
                s3 += p[(size_t)(v + 3) * OUTSZ];
            }
        }
        red[ws * 33 + lane] = (s0 + s1) + (s2 + s3);
        __syncthreads();
        if (ws == 0 && og < OUTSZ) {
            float tot = 0.f;
            #pragma unroll
            for (int j = 0; j < 8; ++j) tot += red[j * 33 + lane];
            out[og] = tot * (1.0f / BB);
        }
        __threadfence();
        __syncthreads();
        if (t == 0) {
            if (atomicAdd(&g_done, 1) == NRED - 1) {   // last reducer resets for replay
                g_ctr  = 0;
                g_done = 0;
            }
        }
        return;
    }

    // ================= WORD BLOCKS =================
    float* Ps  = sm + SM_PS;
    float* U   = sm + SM_U;
    float* V   = sm + SM_V;
    float* Wsh = sm + SM_V;            // alias: W lives here only during phase S
    float* E   = sm + SM_E;
    int*   lab  = (int*)(sm + SM_LAB);
    int*   dexp = (int*)(sm + SM_DEXP);
    int*   cnt  = (int*)(sm + SM_CNT);
    __shared__ int s_is64;

    const int w = blockIdx.x;

    // ---- detect labels dtype (int64 little-endian -> odd int32 words all zero) ----
    if (t == 0) s_is64 = 1;
    __syncthreads();
    if (labI[2*t + 1] != 0) atomicAnd(&s_is64, 0);

    // ---- init: E = exp(T), W -> padded smem, zero counts + dexp ----
    for (int p = t; p < KK*KK; p += 256) { E[p] = __expf(Tg[p]); cnt[p] = 0; }
    for (int p = t; p < KK*DD; p += 256) Wsh[(p / DD) * WPAD + (p % DD)] = Wg[p];
    for (int p = t; p < MM;    p += 256) dexp[p] = 0;
    __syncthreads();
    const int is64 = s_is64;
    for (int p = t; p < MM; p += 256)
        lab[p] = is64 ? labI[((size_t)w*MM + p) * 2] : labI[(size_t)w*MM + p];
    __syncthreads();
    if (t < MM - 1) atomicAdd(&cnt[lab[t]*KK + lab[t+1]], 1);   // exact int, deterministic

    // ---- Phase S: Ps[i][k] = exp(dot(x[i], W[k])) ----
    // SINGLE row per warp-pass (R6 form, measured L2=2.8%): only 1-2 x lines
    // in flight per warp -> no L1 set-conflict thrash (R8/R10's multi-row
    // 512B-strided streams aliased in L1 and pushed L2 to 37%).
    const float* x = data + (size_t)w * MM * DD;
    {
        const int ll = (lane < KK) ? lane : 0;
        const u64* wr = (const u64*)(Wsh + ll * WPAD);
        for (int r = 0; r < MM/8; ++r) {
            const int i = wid * (MM/8) + r;
            const double2* x2 = (const double2*)(x + (size_t)i * DD);
            u64 a0 = 0, a1 = 0;
            #pragma unroll
            for (int p = 0; p < DD/4; ++p) {
                double2 v = __ldg(x2 + p);          // lane-uniform 16B broadcast
                a0 = ffma2((u64)__double_as_longlong(v.x), wr[2*p],     a0);
                a1 = ffma2((u64)__double_as_longlong(v.y), wr[2*p + 1], a1);
            }
            float2 f0 = upk2(a0), f1 = upk2(a1);
            if (lane < KK) Ps[i*KP + lane] = __expf((f0.x + f0.y) + (f1.x + f1.y));
        }
    }
    __syncthreads();   // Ps done; Wsh region now free for V

    // ---- Phase DP: warp0 forward, warp1 backward (linear domain, renorm every 4) ----
    if (wid == 0) {
        const int ll = (lane < KK) ? lane : 0;
        float Ecol[KK];
        #pragma unroll
        for (int j = 0; j < KK; ++j) Ecol[j] = E[j*KK + ll];   // E[y', lane]
        float u = (lane < KK) ? 1.f : 0.f;
        if (lane < KK) U[lane] = 1.f;
        float pcur = Ps[ll];
        for (int i = 1; i < MM; ++i) {
            float tv = (lane < KK) ? u * pcur : 0.f;
            pcur = Ps[i*KP + ll];                     // prefetch row i (used next iter)
            float a0 = 0.f, a1 = 0.f, a2 = 0.f, a3 = 0.f;
            #pragma unroll
            for (int j = 0; j < 24; j += 4) {
                a0 = fmaf(__shfl_sync(0xffffffffu, tv, j+0), Ecol[j+0], a0);
                a1 = fmaf(__shfl_sync(0xffffffffu, tv, j+1), Ecol[j+1], a1);
                a2 = fmaf(__shfl_sync(0xffffffffu, tv, j+2), Ecol[j+2], a2);
                a3 = fmaf(__shfl_sync(0xffffffffu, tv, j+3), Ecol[j+3], a3);
            }
            a0 = fmaf(__shfl_sync(0xffffffffu, tv, 24), Ecol[24], a0);
            a1 = fmaf(__shfl_sync(0xffffffffu, tv, 25), Ecol[25], a1);
            float un = (a0 + a1) + (a2 + a3);
            if ((i & 3) == 0) {                       // exact 2^k renorm, every 4 steps
                unsigned mb = __reduce_max_sync(0xffffffffu, __float_as_uint(un));
                un *= __uint_as_float((254u - (mb >> 23)) << 23);
            }
            u = un;
            if (lane < KK) U[i*KP + lane] = u;
        }
    } else if (wid == 1) {
        const int ll = (lane < KK) ? lane : 0;
        float Erow[KK];
        #pragma unroll
        for (int j = 0; j < KK; ++j) Erow[j] = E[ll*KK + j];   // E[lane, y'']
        float v = (lane < KK) ? 1.f : 0.f;
        if (lane < KK) V[(MM-1)*KP + lane] = 1.f;
        float pcur = Ps[(MM-1)*KP + ll];
        for (int i = MM - 2; i >= 0; --i) {
            float rv = (lane < KK) ? v * pcur : 0.f;
            pcur = Ps[i*KP + ll];                     // prefetch row i (used next iter)
            float a0 = 0.f, a1 = 0.f, a2 = 0.f, a3 = 0.f;
            #pragma unroll
            for (int j = 0; j < 24; j += 4) {
                a0 = fmaf(__shfl_sync(0xffffffffu, rv, j+0), Erow[j+0], a0);
                a1 = fmaf(__shfl_sync(0xffffffffu, rv, j+1), Erow[j+1], a1);
                a2 = fmaf(__shfl_sync(0xffffffffu, rv, j+2), Erow[j+2], a2);
                a3 = fmaf(__shfl_sync(0xffffffffu, rv, j+3), Erow[j+3], a3);
            }
            a0 = fmaf(__shfl_sync(0xffffffffu, rv, 24), Erow[24], a0);
            a1 = fmaf(__shfl_sync(0xffffffffu, rv, 25), Erow[25], a1);
            float vn = (a0 + a1) + (a2 + a3);
            if ((i & 3) == 0) {
                unsigned mb = __reduce_max_sync(0xffffffffu, __float_as_uint(vn));
                int fe = (int)(mb >> 23);
                vn *= __uint_as_float((unsigned)(254 - fe) << 23);
                if (lane == 0) dexp[i] = fe - 127;    // applied exponent e_i (else 0)
            }
            v = vn;
            if (lane < KK) V[i*KP + lane] = v;
        }
    }
    __syncthreads();

    // ---- Residual pass: Rres -> Ps, A -> U, B -> V (in place, per-row) ----
    for (int r = 0; r < MM/8; ++r) {
        const int i = wid * (MM/8) + r;
        float u_ = 0.f, v_ = 0.f, p_ = 0.f, prod = 0.f;
        if (lane < KK) {
            u_ = U[i*KP + lane]; v_ = V[i*KP + lane]; p_ = Ps[i*KP + lane];
            prod = u_ * v_ * p_;
        }
        float z = prod;
        #pragma unroll
        for (int o = 16; o; o >>= 1) z += __shfl_xor_sync(0xffffffffu, z, o);
        float inv = 1.f / z;                           // 1 / z_i
        if (lane < KK) {
            float p1 = prod * inv;
            float oh = (lab[i] == lane) ? 1.f : 0.f;
            float sc = __uint_as_float((unsigned)(127 - dexp[i]) << 23);  // exact 2^-e
            Ps[i*KP + lane] = oh - p1;                 // Rres
            U[i*KP + lane]  = u_ * p_ * inv * sc;      // A
            V[i*KP + lane]  = p_ * v_;                 // B
        } else {
            Ps[i*KP + lane] = 0.f;                     // zero pad (dw reads pairs k26..k27)
        }
    }
    __syncthreads();

    float* outw = g_scratch + (size_t)w * OUTSZ;

    // ---- dT: counts - E .* sum_i A[i]^T B[i+1] (packed over b-pairs) ----
    for (int pp = t; pp < (KK*KK)/2; pp += 256) {
        const int a = pp / (KK/2);
        const int q = pp - a * (KK/2);                 // b pair = (2q, 2q+1)
        u64 s2 = 0;
        const float* Ua = U + a;
        const u64*   Vq = (const u64*)(V + 2*q);       // row i at offset i*(KP/2)
        #pragma unroll 4
        for (int i = 0; i < MM - 1; ++i) {
            float uu = Ua[i*KP];
            s2 = ffma2(pk2(uu, uu), Vq[(i+1)*(KP/2)], s2);
        }
        float2 s = upk2(s2);
        const int b0 = 2*q;
        outw[KK*DD + a*KK + b0]     = (float)cnt[a*KK + b0]     - E[a*KK + b0]     * s.x;
        outw[KK*DD + a*KK + b0 + 1] = (float)cnt[a*KK + b0 + 1] - E[a*KK + b0 + 1] * s.y;
    }

    // ---- dw: Rres^T @ x  (broadcast LDS.128 -> u64 pairs, no MOVs) ----
    {
        const int d    = t & (DD - 1);
        const int half = t >> 7;           // 0: k 0..13 (7 pairs), 1: k 14..25 (6 pairs)
        const int np   = 7 - half;
        u64 acc[7];
        #pragma unroll
        for (int j = 0; j < 7; ++j) acc[j] = 0;
        const float* xp = x + d;
        #pragma unroll 2
        for (int i = 0; i < MM; ++i) {
            float xv = __ldg(xp + (size_t)i * DD);     // coalesced across lanes
            u64 xx = pk2(xv, xv);
            const ulonglong2* rp = (const ulonglong2*)(Ps + i*KP) + half * 3;
            ulonglong2 q0 = rp[0], q1 = rp[1], q2 = rp[2], q3 = rp[3];  // 4 bcast LDS.128
            u64 pr[8] = {q0.x, q0.y, q1.x, q1.y, q2.x, q2.y, q3.x, q3.y};
            #pragma unroll
            for (int j = 0; j < 7; ++j)
                if (j < np) acc[j] = ffma2(pr[j + half], xx, acc[j]);
        }
        #pragma unroll
        for (int j = 0; j < 7; ++j) {
            if (j < np) {
                float2 f = upk2(acc[j]);
                const int k = half * 14 + 2 * j;
                outw[(k)     * DD + d] = f.x;
                outw[(k + 1) * DD + d] = f.y;
            }
        }
    }

    // ---- doorbell: this word's gradients are globally visible ----
    __syncthreads();
    if (t == 0) {
        __threadfence();              // release scratch writes
        atomicAdd(&g_ctr, 1);
    }
}

extern "C" void kernel_launch(void* const* d_in, const int* in_sizes, int n_in,
                              void* d_out, int out_size)
{
    const float* data   = (const float*)d_in[0];
    const int*   labels = (const int*)d_in[1];
    const float* W      = (const float*)d_in[2];
    const float* T      = (const float*)d_in[3];
    float* out = (float*)d_out;

    const size_t smem = SM_TOT * sizeof(float);
    cudaFuncSetAttribute(crf_fused_kernel,
                         cudaFuncAttributeMaxDynamicSharedMemorySize, (int)smem);
    crf_fused_kernel<<<BB + NRED, 256, smem>>>(data, labels, W, T, out);
}

// round 13
// speedup vs baseline: 2.2293x; 2.2293x over previous
#include <cuda_runtime.h>
#include <cuda_bf16.h>

#define KK 26
#define DD 128
#define MM 256
#define BB 512
#define NRED 126         // reducer blocks (126*32 >= 4004 outputs)
#define KP 28            // padded row stride (8B-aligned rows); 2x93.5KB smem keeps L1D carveout
#define WPAD 130         // padded W row stride (conflict-free LDS.64 per 16-lane phase)
#define OUTSZ (KK*DD + KK*KK)   // 4004

typedef unsigned long long u64;

__device__ float g_scratch[BB * OUTSZ];   // per-word gradients
__device__ int g_ctr  = 0;                // word-completion doorbell
__device__ int g_done = 0;                // reducer-completion counter

// ---- packed f32x2 helpers (FFMA2 path, sm_100a) ----
__device__ __forceinline__ u64 ffma2(u64 a, u64 b, u64 c) {
    u64 d;
    asm("fma.rn.f32x2 %0, %1, %2, %3;" : "=l"(d) : "l"(a), "l"(b), "l"(c));
    return d;
}
__device__ __forceinline__ u64 pk2(float lo, float hi) {
    u64 r; asm("mov.b64 %0, {%1, %2};" : "=l"(r) : "f"(lo), "f"(hi)); return r;
}
__device__ __forceinline__ float2 upk2(u64 v) {
    float2 f; asm("mov.b64 {%0, %1}, %2;" : "=f"(f.x), "=f"(f.y) : "l"(v)); return f;
}
__device__ __forceinline__ int ld_vol(const int* p) {
    int v; asm volatile("ld.volatile.global.s32 %0, [%1];" : "=r"(v) : "l"(p)); return v;
}

// ---- dynamic shared memory layout (floats) ----
#define SM_PS   0                      // [MM][KP] Ps, later Rres
#define SM_U    (SM_PS + MM*KP)        // [MM][KP] U,  later A
#define SM_V    (SM_U  + MM*KP)        // [MM][KP] V,  later B  (aliases Wsh in phase S)
#define SM_E    (SM_V  + MM*KP)        // [KK*KK]  exp(T)
#define SM_LAB  (SM_E  + KK*KK)        // [MM] int labels
#define SM_DEXP (SM_LAB + MM)          // [MM] int backward scale exponents
#define SM_CNT  (SM_DEXP + MM)         // [KK*KK] int transition counts
#define SM_TOT  (SM_CNT + KK*KK)       // 23368 floats = 93472 bytes

__global__ void __launch_bounds__(256, 2)
crf_fused_kernel(const float* __restrict__ data,
                 const int* __restrict__ labI,
                 const float* __restrict__ Wg,
                 const float* __restrict__ Tg,
                 float* __restrict__ out)
{
    extern __shared__ float sm[];
    const int t    = threadIdx.x;
    const int lane = t & 31;
    const int wid  = t >> 5;

    // ================= REDUCER BLOCKS =================
    if (blockIdx.x >= BB) {
        if (t == 0) {
            while (ld_vol(&g_ctr) < BB) __nanosleep(200);
        }
        __syncthreads();
        __threadfence();   // acquire: order scratch reads after doorbell

        float* red = sm;   // [8][33]
        const int ws = wid;
        const int og = (blockIdx.x - BB) * 32 + lane;
        float s0 = 0.f, s1 = 0.f, s2 = 0.f, s3 = 0.f;
        if (og < OUTSZ) {
            const float* p = g_scratch + (size_t)ws * 64 * OUTSZ + og;
            #pragma unroll 4
            for (int v = 0; v < 64; v += 4) {
                s0 += p[(size_t)(v + 0) * OUTSZ];
                s1 += p[(size_t)(v + 1) * OUTSZ];
                s2 += p[(size_t)(v + 2) * OUTSZ];
                s3 += p[(size_t)(v + 3) * OUTSZ];
            }
        }
        red[ws * 33 + lane] = (s0 + s1) + (s2 + s3);
        __syncthreads();
        if (ws == 0 && og < OUTSZ) {
            float tot = 0.f;
            #pragma unroll
            for (int j = 0; j < 8; ++j) tot += red[j * 33 + lane];
            out[og] = tot * (1.0f / BB);
        }
        __threadfence();
        __syncthreads();
        if (t == 0) {
            if (atomicAdd(&g_done, 1) == NRED - 1) {   // last reducer resets for replay
                g_ctr  = 0;
                g_done = 0;
            }
        }
        return;
    }

    // ================= WORD BLOCKS =================
    float* Ps  = sm + SM_PS;
    float* U   = sm + SM_U;
    float* V   = sm + SM_V;
    float* Wsh = sm + SM_V;            // alias: W lives here only during phase S
    float* E   = sm + SM_E;
    int*   lab  = (int*)(sm + SM_LAB);
    int*   dexp = (int*)(sm + SM_DEXP);
    int*   cnt  = (int*)(sm + SM_CNT);
    __shared__ int s_is64;

    const int w = blockIdx.x;

    // ---- detect labels dtype (int64 little-endian -> odd int32 words all zero) ----
    if (t == 0) s_is64 = 1;
    __syncthreads();
    if (labI[2*t + 1] != 0) atomicAnd(&s_is64, 0);

    // ---- init: E = exp(T), W -> padded smem, zero counts + dexp ----
    for (int p = t; p < KK*KK; p += 256) { E[p] = __expf(Tg[p]); cnt[p] = 0; }
    for (int p = t; p < KK*DD; p += 256) Wsh[(p / DD) * WPAD + (p % DD)] = Wg[p];
    for (int p = t; p < MM;    p += 256) dexp[p] = 0;
    __syncthreads();
    const int is64 = s_is64;
    for (int p = t; p < MM; p += 256)
        lab[p] = is64 ? labI[((size_t)w*MM + p) * 2] : labI[(size_t)w*MM + p];
    __syncthreads();
    if (t < MM - 1) atomicAdd(&cnt[lab[t]*KK + lab[t+1]], 1);   // exact int, deterministic

    // ---- Phase S: Ps[i][k] = exp(dot(x[i], W[k])) -- 8 rows per W pass ----
    // Each W pair is read ONCE for 8 rows (phase-S wavefronts halved vs single-row).
    // KP=28 keeps smem at 187KB/SM -> L1D carveout intact (KP=32's 211.5KB zeroed
    // L1D and pushed all x loads to L2: the R8/R10/R12 ~200us regression).
    const float* x = data + (size_t)w * MM * DD;
    {
        const int ll = (lane < KK) ? lane : 0;
        const u64* wr = (const u64*)(Wsh + ll * WPAD);
        const int i0 = wid * 32;
        for (int g = 0; g < 4; ++g) {
            const int ib = i0 + g * 8;
            const double2* xb = (const double2*)(x + (size_t)ib * DD);  // row stride DD/4 double2
            u64 acc[8];
            #pragma unroll
            for (int r = 0; r < 8; ++r) acc[r] = 0;
            #pragma unroll 4
            for (int p = 0; p < DD/4; ++p) {
                u64 w0 = wr[2*p], w1 = wr[2*p + 1];
                #pragma unroll
                for (int r = 0; r < 8; ++r) {
                    double2 v = __ldg(xb + (size_t)r * (DD/4) + p);  // 16B lane-uniform broadcast
                    acc[r] = ffma2((u64)__double_as_longlong(v.x), w0, acc[r]);
                    acc[r] = ffma2((u64)__double_as_longlong(v.y), w1, acc[r]);
                }
            }
            if (lane < KK) {
                #pragma unroll
                for (int r = 0; r < 8; ++r) {
                    float2 f = upk2(acc[r]);
                    Ps[(ib + r)*KP + lane] = __expf(f.x + f.y);
                }
            }
        }
    }
    __syncthreads();   // Ps done; Wsh region now free for V

    // ---- Phase DP: warp0 forward, warp1 backward (linear domain, renorm every 4) ----
    if (wid == 0) {
        const int ll = (lane < KK) ? lane : 0;
        float Ecol[KK];
        #pragma unroll
        for (int j = 0; j < KK; ++j) Ecol[j] = E[j*KK + ll];   // E[y', lane]
        float u = (lane < KK) ? 1.f : 0.f;
        if (lane < KK) U[lane] = 1.f;
        float pcur = Ps[ll];
        for (int i = 1; i < MM; ++i) {
            float tv = (lane < KK) ? u * pcur : 0.f;
            pcur = Ps[i*KP + ll];                     // prefetch row i (used next iter)
            float a0 = 0.f, a1 = 0.f, a2 = 0.f, a3 = 0.f;
            #pragma unroll
            for (int j = 0; j < 24; j += 4) {
                a0 = fmaf(__shfl_sync(0xffffffffu, tv, j+0), Ecol[j+0], a0);
                a1 = fmaf(__shfl_sync(0xffffffffu, tv, j+1), Ecol[j+1], a1);
                a2 = fmaf(__shfl_sync(0xffffffffu, tv, j+2), Ecol[j+2], a2);
                a3 = fmaf(__shfl_sync(0xffffffffu, tv, j+3), Ecol[j+3], a3);
            }
            a0 = fmaf(__shfl_sync(0xffffffffu, tv, 24), Ecol[24], a0);
            a1 = fmaf(__shfl_sync(0xffffffffu, tv, 25), Ecol[25], a1);
            float un = (a0 + a1) + (a2 + a3);
            if ((i & 3) == 0) {                       // exact 2^k renorm, every 4 steps
                unsigned mb = __reduce_max_sync(0xffffffffu, __float_as_uint(un));
                un *= __uint_as_float((254u - (mb >> 23)) << 23);
            }
            u = un;
            if (lane < KK) U[i*KP + lane] = u;
        }
    } else if (wid == 1) {
        const int ll = (lane < KK) ? lane : 0;
        float Erow[KK];
        #pragma unroll
        for (int j = 0; j < KK; ++j) Erow[j] = E[ll*KK + j];   // E[lane, y'']
        float v = (lane < KK) ? 1.f : 0.f;
        if (lane < KK) V[(MM-1)*KP + lane] = 1.f;
        float pcur = Ps[(MM-1)*KP + ll];
        for (int i = MM - 2; i >= 0; --i) {
            float rv = (lane < KK) ? v * pcur : 0.f;
            pcur = Ps[i*KP + ll];                     // prefetch row i (used next iter)
            float a0 = 0.f, a1 = 0.f, a2 = 0.f, a3 = 0.f;
            #pragma unroll
            for (int j = 0; j < 24; j += 4) {
                a0 = fmaf(__shfl_sync(0xffffffffu, rv, j+0), Erow[j+0], a0);
                a1 = fmaf(__shfl_sync(0xffffffffu, rv, j+1), Erow[j+1], a1);
                a2 = fmaf(__shfl_sync(0xffffffffu, rv, j+2), Erow[j+2], a2);
                a3 = fmaf(__shfl_sync(0xffffffffu, rv, j+3), Erow[j+3], a3);
            }
            a0 = fmaf(__shfl_sync(0xffffffffu, rv, 24), Erow[24], a0);
            a1 = fmaf(__shfl_sync(0xffffffffu, rv, 25), Erow[25], a1);
            float vn = (a0 + a1) + (a2 + a3);
            if ((i & 3) == 0) {
                unsigned mb = __reduce_max_sync(0xffffffffu, __float_as_uint(vn));
                int fe = (int)(mb >> 23);
                vn *= __uint_as_float((unsigned)(254 - fe) << 23);
                if (lane == 0) dexp[i] = fe - 127;    // applied exponent e_i (else 0)
            }
            v = vn;
            if (lane < KK) V[i*KP + lane] = v;
        }
    }
    __syncthreads();

    // ---- Residual pass: Rres -> Ps, A -> U, B -> V (in place, per-row) ----
    for (int r = 0; r < MM/8; ++r) {
        const int i = wid * (MM/8) + r;
        float u_ = 0.f, v_ = 0.f, p_ = 0.f, prod = 0.f;
        if (lane < KK) {
            u_ = U[i*KP + lane]; v_ = V[i*KP + lane]; p_ = Ps[i*KP + lane];
            prod = u_ * v_ * p_;
        }
        float z = prod;
        #pragma unroll
        for (int o = 16; o; o >>= 1) z += __shfl_xor_sync(0xffffffffu, z, o);
        float inv = 1.f / z;                           // 1 / z_i
        if (lane < KK) {
            float p1 = prod * inv;
            float oh = (lab[i] == lane) ? 1.f : 0.f;
            float sc = __uint_as_float((unsigned)(127 - dexp[i]) << 23);  // exact 2^-e
            Ps[i*KP + lane] = oh - p1;                 // Rres
            U[i*KP + lane]  = u_ * p_ * inv * sc;      // A
            V[i*KP + lane]  = p_ * v_;                 // B
        }
    }
    __syncthreads();

    float* outw = g_scratch + (size_t)w * OUTSZ;

    // ---- dT: counts - E .* sum_i A[i]^T B[i+1] (packed over b-pairs) ----
    for (int pp = t; pp < (KK*KK)/2; pp += 256) {
        const int a = pp / (KK/2);
        const int q = pp - a * (KK/2);                 // b pair = (2q, 2q+1)
        u64 s2 = 0;
        const float* Ua = U + a;
        const u64*   Vq = (const u64*)(V + 2*q);       // row i at offset i*(KP/2)
        #pragma unroll 4
        for (int i = 0; i < MM - 1; ++i) {
            float uu = Ua[i*KP];
            s2 = ffma2(pk2(uu, uu), Vq[(i+1)*(KP/2)], s2);
        }
        float2 s = upk2(s2);
        const int b0 = 2*q;
        outw[KK*DD + a*KK + b0]     = (float)cnt[a*KK + b0]     - E[a*KK + b0]     * s.x;
        outw[KK*DD + a*KK + b0 + 1] = (float)cnt[a*KK + b0 + 1] - E[a*KK + b0 + 1] * s.y;
    }

    // ---- dw: Rres^T @ x (packed over k-pairs, LDS.64 broadcast, KP=28-safe) ----
    {
        const int d    = t & (DD - 1);
        const int half = t >> 7;                       // 0: k 0..13 (7 pairs), 1: k 14..25 (6 pairs)
        const int p0   = half * 7;
        const int np   = 7 - half;
        u64 acc[7];
        #pragma unroll
        for (int j = 0; j < 7; ++j) acc[j] = 0;
        const float* xp = x + d;
        for (int i = 0; i < MM; i += 2) {
            float xv0 = __ldg(xp + (size_t)i * DD);
            float xv1 = __ldg(xp + (size_t)(i+1) * DD);
            u64 xx0 = pk2(xv0, xv0), xx1 = pk2(xv1, xv1);
            const u64* r0 = (const u64*)(Ps + i*KP) + p0;
            const u64* r1 = (const u64*)(Ps + (i+1)*KP) + p0;
            #pragma unroll
            for (int j = 0; j < 7; ++j) {
                if (j < np) {
                    acc[j] = ffma2(r0[j], xx0, acc[j]);
                    acc[j] = ffma2(r1[j], xx1, acc[j]);
                }
            }
        }
        #pragma unroll
        for (int j = 0; j < 7; ++j) {
            if (j < np) {
                float2 f = upk2(acc[j]);
                const int k = 2 * (p0 + j);
                outw[(k)     * DD + d] = f.x;
                outw[(k + 1) * DD + d] = f.y;
            }
        }
    }

    // ---- doorbell: this word's gradients are globally visible ----
    __syncthreads();
    if (t == 0) {
        __threadfence();              // release scratch writes
        atomicAdd(&g_ctr, 1);
    }
}

extern "C" void kernel_launch(void* const* d_in, const int* in_sizes, int n_in,
                              void* d_out, int out_size)
{
    const float* data   = (const float*)d_in[0];
    const int*   labels = (const int*)d_in[1];
    const float* W      = (const float*)d_in[2];
    const float* T      = (const float*)d_in[3];
    float* out = (float*)d_out;

    const size_t smem = SM_TOT * sizeof(float);
    cudaFuncSetAttribute(crf_fused_kernel,
                         cudaFuncAttributeMaxDynamicSharedMemorySize, (int)smem);
    crf_fused_kernel<<<BB + NRED, 256, smem>>>(data, labels, W, T, out);
}